// round 16
// baseline (speedup 1.0000x reference)
#include <cuda_runtime.h>
#include <mma.h>
#include <math.h>
#include <stdint.h>

using namespace nvcuda;

#define CB  32
#define CNS 4096
#define CD  256
#define CH  4
#define CDH 64
#define CL  6
#define CNQ 512
#define CNK 1024
#define SCALE_F 0.125f   // 1/sqrt(64)
#define NKW (CNK/32)     // mask words per q row

// ------------------------- scratch (device globals; no allocs) -------------
__device__ float g_upd[CB*CNS*CD];
__device__ float g_q  [CB*CNQ*CD];
__device__ float g_k  [CB*CNK*CD];
__device__ float g_Qp [CB*CNQ*CD];
__device__ float g_Kp [CB*CNK*CD];
__device__ float g_Vp [CB*CNK*CD];
__device__ float g_ctx[CB*CNQ*CD];
__device__ float g_h  [CB*CNQ*CD];
__device__ float g_t1 [CB*CNQ*CD];
__device__ uint32_t g_mbits[CL*CNQ*NKW];   // packed mask bits

// ------------------------- helpers ----------------------------------------
__device__ __forceinline__ float gelu_tanh(float x){
    float x3 = x*x*x;
    float t  = tanhf(0.7978845608028654f * (x + 0.044715f * x3));
    return 0.5f * x * (1.0f + t);
}
__device__ __forceinline__ float to_tf32(float x){
    return wmma::__float_to_tf32(x);
}

// ------------------------- init copy ---------------------------------------
__global__ void k_copy_upd(const float4* __restrict__ src){
    size_t i = (size_t)blockIdx.x * blockDim.x + threadIdx.x;
    ((float4*)g_upd)[i] = src[i];
}

// ------------------------- mask prep: floats -> bitmask --------------------
__global__ void k_prep_mask(const float* __restrict__ m){
    int i = blockIdx.x * 256 + threadIdx.x;     // word idx, CL*CNQ*NKW total
    const float4* src = (const float4*)m + (size_t)i*8;
    uint32_t bits = 0;
    #pragma unroll
    for(int j=0;j<8;j++){
        float4 v = src[j];
        bits |= (v.x > 0.5f ? 1u : 0u) << (j*4 + 0);
        bits |= (v.y > 0.5f ? 1u : 0u) << (j*4 + 1);
        bits |= (v.z > 0.5f ? 1u : 0u) << (j*4 + 2);
        bits |= (v.w > 0.5f ? 1u : 0u) << (j*4 + 3);
    }
    g_mbits[i] = bits;
}

// ------------------------- gather + LayerNorm ------------------------------
__global__ void k_gather_ln(const float* __restrict__ upd,
                            const float* __restrict__ emb,
                            const int*   __restrict__ idx,
                            const float* __restrict__ sc,
                            const float* __restrict__ bi,
                            float* __restrict__ out, int N){
    __shared__ float sbuf[16];
    int row = blockIdx.x;
    int b = row / N, p = row - b*N;
    int node = idx[p];
    int t = threadIdx.x;
    float x = emb[(size_t)node*CD + t] + upd[((size_t)b*CNS + node)*CD + t];
    float s1 = x, s2 = x*x;
    #pragma unroll
    for(int o=16;o>0;o>>=1){
        s1 += __shfl_xor_sync(0xffffffffu, s1, o);
        s2 += __shfl_xor_sync(0xffffffffu, s2, o);
    }
    if((t&31)==0){ sbuf[t>>5]=s1; sbuf[8+(t>>5)]=s2; }
    __syncthreads();
    s1=0.f; s2=0.f;
    #pragma unroll
    for(int i=0;i<8;i++){ s1+=sbuf[i]; s2+=sbuf[8+i]; }
    float mean = s1 * (1.0f/CD);
    float var  = s2 * (1.0f/CD) - mean*mean;
    float rstd = rsqrtf(var + 1e-5f);
    out[(size_t)row*CD + t] = (x-mean)*rstd*sc[t] + bi[t];
}

// ===================== TF32 WMMA dense GEMM (round-6 proven) ===============
// C[M,256] = A[M,256] @ W[256,256] (+bias)(+gelu). 8 warps as 4x2,
// warp tile 32x64 = 2x4 m16n16k8 frags. Static 44KB smem, sync staging.
__global__ void __launch_bounds__(256)
k_gemm_tc(const float* __restrict__ A, const float* __restrict__ W,
          const float* __restrict__ bias, float* __restrict__ C, int act){
    __shared__ __align__(16) float As[128][36];
    __shared__ __align__(16) float Bs[32][132];
    __shared__ __align__(16) float BiasS[16][132];
    int tid = threadIdx.x;
    int w = tid >> 5;
    int wy = w >> 1, wx = w & 1;           // 4 x 2 warps
    int bm0 = blockIdx.x * 128;
    int bn0 = blockIdx.y * 128;

    wmma::fragment<wmma::accumulator,16,16,8,float> acc[2][4];
    #pragma unroll
    for(int i=0;i<2;i++)
        #pragma unroll
        for(int j=0;j<4;j++) wmma::fill_fragment(acc[i][j], 0.0f);

    for(int k0=0;k0<CD;k0+=32){
        #pragma unroll
        for(int i=0;i<4;i++){
            int id = tid + i*256;
            int r = id >> 3, c4 = id & 7;
            float4 v = *(const float4*)&A[(size_t)(bm0+r)*CD + k0 + c4*4];
            float* d = &As[r][c4*4];
            d[0]=to_tf32(v.x); d[1]=to_tf32(v.y); d[2]=to_tf32(v.z); d[3]=to_tf32(v.w);
        }
        #pragma unroll
        for(int i=0;i<4;i++){
            int id = tid + i*256;
            int r = id >> 5, c4 = id & 31;
            float4 v = *(const float4*)&W[(size_t)(k0+r)*CD + bn0 + c4*4];
            float* d = &Bs[r][c4*4];
            d[0]=to_tf32(v.x); d[1]=to_tf32(v.y); d[2]=to_tf32(v.z); d[3]=to_tf32(v.w);
        }
        __syncthreads();
        #pragma unroll
        for(int ks=0;ks<4;ks++){
            wmma::fragment<wmma::matrix_a,16,16,8,wmma::precision::tf32,wmma::row_major> af[2];
            wmma::fragment<wmma::matrix_b,16,16,8,wmma::precision::tf32,wmma::row_major> bf[4];
            wmma::load_matrix_sync(af[0], &As[wy*32][ks*8],    36);
            wmma::load_matrix_sync(af[1], &As[wy*32+16][ks*8], 36);
            #pragma unroll
            for(int j=0;j<4;j++)
                wmma::load_matrix_sync(bf[j], &Bs[ks*8][wx*64 + j*16], 132);
            #pragma unroll
            for(int i=0;i<2;i++)
                #pragma unroll
                for(int j=0;j<4;j++)
                    wmma::mma_sync(acc[i][j], af[i], bf[j], acc[i][j]);
        }
        __syncthreads();
    }

    if(bias){
        #pragma unroll
        for(int i=0;i<8;i++){
            int id = tid + i*256;      // 16x128
            int r = id >> 7, c = id & 127;
            BiasS[r][c] = bias[bn0 + c];
        }
        __syncthreads();
        #pragma unroll
        for(int j=0;j<4;j++){
            wmma::fragment<wmma::accumulator,16,16,8,float> bfr;
            wmma::load_matrix_sync(bfr, &BiasS[0][wx*64 + j*16], 132, wmma::mem_row_major);
            #pragma unroll
            for(int i=0;i<2;i++)
                #pragma unroll
                for(int e=0;e<bfr.num_elements;e++)
                    acc[i][j].x[e] += bfr.x[e];
        }
    }
    if(act==1){
        #pragma unroll
        for(int i=0;i<2;i++)
            #pragma unroll
            for(int j=0;j<4;j++)
                #pragma unroll
                for(int e=0;e<acc[i][j].num_elements;e++)
                    acc[i][j].x[e] = gelu_tanh(acc[i][j].x[e]);
    }
    #pragma unroll
    for(int i=0;i<2;i++)
        #pragma unroll
        for(int j=0;j<4;j++)
            wmma::store_matrix_sync(
                &C[(size_t)(bm0 + wy*32 + i*16)*CD + bn0 + wx*64 + j*16],
                acc[i][j], CD, wmma::mem_row_major);
}

// ===================== epilogue-fused GEMM (64x256 full-row blocks) ========
// mode 0: out0 = LN(A@W ; s1,b1)                      [Wo + inner LN -> hb]
// mode 1: x = h + (A@W + bias); y = LN(x; s1,b1);
//         res = LN(y; s2,b2); atomicAdd(out0[scatter], res); same out1.
// 8 warps as 2x4, warp tile 32x64 = 2x4 frags. Dynamic smem 66.6KB.
#define EP_MAIN_FLOATS (64*36 + 32*260)
#define EP_CS_FLOATS   (64*260)
#define EP_SMEM_FLOATS (EP_CS_FLOATS > EP_MAIN_FLOATS ? EP_CS_FLOATS : EP_MAIN_FLOATS)
__global__ void __launch_bounds__(256)
k_gemm_ep(const float* __restrict__ A, const float* __restrict__ W,
          const float* __restrict__ bias, const float* __restrict__ h,
          const float* __restrict__ s1v, const float* __restrict__ b1v,
          const float* __restrict__ s2v, const float* __restrict__ b2v,
          const int*   __restrict__ qidx,
          float* __restrict__ out0, float* __restrict__ out1, int mode){
    extern __shared__ __align__(16) float esm[];
    float* As = esm;              // [64][36]
    float* Bs = esm + 64*36;      // [32][260]
    int tid = threadIdx.x;
    int w = tid >> 5, lane = tid & 31;
    int wy = w >> 2, wx = w & 3;           // 2 x 4 warps
    int bm0 = blockIdx.x * 64;

    wmma::fragment<wmma::accumulator,16,16,8,float> acc[2][4];
    #pragma unroll
    for(int i=0;i<2;i++)
        #pragma unroll
        for(int j=0;j<4;j++) wmma::fill_fragment(acc[i][j], 0.0f);

    for(int k0=0;k0<CD;k0+=32){
        // A tile 64x32 (2 passes)
        #pragma unroll
        for(int i=0;i<2;i++){
            int id = tid + i*256;
            int r = id >> 3, c4 = id & 7;
            float4 v = *(const float4*)&A[(size_t)(bm0+r)*CD + k0 + c4*4];
            float* d = &As[r*36 + c4*4];
            d[0]=to_tf32(v.x); d[1]=to_tf32(v.y); d[2]=to_tf32(v.z); d[3]=to_tf32(v.w);
        }
        // B tile 32x256 (8 passes)
        #pragma unroll
        for(int i=0;i<8;i++){
            int id = tid + i*256;
            int r = id >> 6, c4 = id & 63;
            float4 v = *(const float4*)&W[(size_t)(k0+r)*CD + c4*4];
            float* d = &Bs[r*260 + c4*4];
            d[0]=to_tf32(v.x); d[1]=to_tf32(v.y); d[2]=to_tf32(v.z); d[3]=to_tf32(v.w);
        }
        __syncthreads();
        #pragma unroll
        for(int ks=0;ks<4;ks++){
            wmma::fragment<wmma::matrix_a,16,16,8,wmma::precision::tf32,wmma::row_major> af[2];
            wmma::fragment<wmma::matrix_b,16,16,8,wmma::precision::tf32,wmma::row_major> bf[4];
            wmma::load_matrix_sync(af[0], &As[(wy*32)*36 + ks*8],    36);
            wmma::load_matrix_sync(af[1], &As[(wy*32+16)*36 + ks*8], 36);
            #pragma unroll
            for(int j=0;j<4;j++)
                wmma::load_matrix_sync(bf[j], &Bs[(ks*8)*260 + wx*64 + j*16], 260);
            #pragma unroll
            for(int i=0;i<2;i++)
                #pragma unroll
                for(int j=0;j<4;j++)
                    wmma::mma_sync(acc[i][j], af[i], bf[j], acc[i][j]);
        }
        __syncthreads();
    }

    // ---- epilogue: acc -> Cs (overlays As/Bs; all mainloop reads done) ----
    float* Cs = esm;              // [64][260]
    #pragma unroll
    for(int i=0;i<2;i++)
        #pragma unroll
        for(int j=0;j<4;j++)
            wmma::store_matrix_sync(&Cs[(wy*32+i*16)*260 + wx*64 + j*16],
                                    acc[i][j], 260, wmma::mem_row_major);
    __syncthreads();

    // per-warp rows: warp w owns rows w*8..w*8+7; lane owns 8 contiguous cols
    int c0 = lane*8;
    #pragma unroll
    for(int r=0;r<8;r++){
        int row  = w*8 + r;
        int grow = bm0 + row;
        float v[8];
        *(float4*)&v[0] = *(float4*)&Cs[row*260 + c0];
        *(float4*)&v[4] = *(float4*)&Cs[row*260 + c0 + 4];
        if(mode==1){
            float4 bb0 = *(const float4*)&bias[c0];
            float4 bb1 = *(const float4*)&bias[c0+4];
            v[0]+=bb0.x; v[1]+=bb0.y; v[2]+=bb0.z; v[3]+=bb0.w;
            v[4]+=bb1.x; v[5]+=bb1.y; v[6]+=bb1.z; v[7]+=bb1.w;
            float4 hh0 = *(const float4*)&h[(size_t)grow*CD + c0];
            float4 hh1 = *(const float4*)&h[(size_t)grow*CD + c0 + 4];
            v[0]+=hh0.x; v[1]+=hh0.y; v[2]+=hh0.z; v[3]+=hh0.w;
            v[4]+=hh1.x; v[5]+=hh1.y; v[6]+=hh1.z; v[7]+=hh1.w;
        }
        // LN 1
        float s1 = 0.f, s2 = 0.f;
        #pragma unroll
        for(int e=0;e<8;e++){ s1 += v[e]; s2 += v[e]*v[e]; }
        #pragma unroll
        for(int o=16;o>0;o>>=1){
            s1 += __shfl_xor_sync(0xffffffffu, s1, o);
            s2 += __shfl_xor_sync(0xffffffffu, s2, o);
        }
        float mean = s1*(1.0f/CD);
        float var  = s2*(1.0f/CD) - mean*mean;
        float rstd = rsqrtf(var + 1e-5f);
        float y[8];
        #pragma unroll
        for(int e=0;e<8;e++)
            y[e] = (v[e]-mean)*rstd*s1v[c0+e] + b1v[c0+e];

        if(mode==0){
            *(float4*)&out0[(size_t)grow*CD + c0]     = *(float4*)&y[0];
            *(float4*)&out0[(size_t)grow*CD + c0 + 4] = *(float4*)&y[4];
        }else{
            // LN 2
            float t1s = 0.f, t2s = 0.f;
            #pragma unroll
            for(int e=0;e<8;e++){ t1s += y[e]; t2s += y[e]*y[e]; }
            #pragma unroll
            for(int o=16;o>0;o>>=1){
                t1s += __shfl_xor_sync(0xffffffffu, t1s, o);
                t2s += __shfl_xor_sync(0xffffffffu, t2s, o);
            }
            float mean2 = t1s*(1.0f/CD);
            float var2  = t2s*(1.0f/CD) - mean2*mean2;
            float rstd2 = rsqrtf(var2 + 1e-5f);
            int bI = grow >> 9, p = grow & (CNQ-1);
            int node = qidx[p];
            size_t off = ((size_t)(bI*CNS + node))*CD + c0;
            #pragma unroll
            for(int e=0;e<8;e++){
                float res = (y[e]-mean2)*rstd2*s2v[c0+e] + b2v[c0+e];
                atomicAdd(&out0[off+e], res);
                atomicAdd(&out1[off+e], res);
            }
        }
    }
}

// ===================== fused flash attention (512 thr, 128 q-rows) =========
// grid (NQ/128, B*H), 512 thr = 16 warps. Q tile 128 rows, K tiles of 128.
// Bitmask mask: 1 LDG.32/lane/tile. (Round-15 proven.)
#define FLASH_SMEM_FLOATS (128*68 + 128*68 + 128*132 + 128*20)
__global__ void __launch_bounds__(512)
k_flash(const float* __restrict__ Q, const float* __restrict__ K,
        const float* __restrict__ V, const uint32_t* __restrict__ mbits,
        float* __restrict__ ctx){
    extern __shared__ __align__(16) float sm[];
    float* Qs  = sm;                    // [128][68]  q (pre-scaled, tf32)
    float* KVs = Qs  + 128*68;          // [128][68]  K then V (tf32)
    float* Ss  = KVs + 128*68;          // [128][132] scores -> probs
    float* aM  = Ss  + 128*132;         // [128][20]  per-row alpha / inv-denom

    int tid = threadIdx.x;
    int w = tid >> 5, lane = tid & 31;
    int wy = w >> 2, wx = w & 3;        // S phase: 4x4 warps (32q x 32k)
    int wq = w >> 1, wd = w & 1;        // PV phase: 8x2 warps (16q x 32d)
    int q0 = blockIdx.x * 128;
    int bh = blockIdx.y;
    int b = bh >> 2, h = bh & 3;

    const float* Qb = Q + ((size_t)(b*CNQ + q0))*CD + h*CDH;
    const float* Kb = K + ((size_t)b*CNK)*CD + h*CDH;
    const float* Vb = V + ((size_t)b*CNK)*CD + h*CDH;

    const int srow = w*8 + (lane >> 2);
    const int sqtr = lane & 3;
    const uint32_t* mrow = mbits + (size_t)(q0+srow)*NKW;

    #pragma unroll
    for(int i=0;i<4;i++){
        int id = tid + i*512;
        int r = id >> 4, c4 = id & 15;
        float4 v = *(const float4*)&Qb[(size_t)r*CD + c4*4];
        float* d = &Qs[r*68 + c4*4];
        d[0]=to_tf32(v.x*SCALE_F); d[1]=to_tf32(v.y*SCALE_F);
        d[2]=to_tf32(v.z*SCALE_F); d[3]=to_tf32(v.w*SCALE_F);
    }
    #pragma unroll
    for(int i=0;i<4;i++){
        int id = tid + i*512;
        int r = id >> 4, c4 = id & 15;
        float4 v = *(const float4*)&Kb[(size_t)r*CD + c4*4];
        float* d = &KVs[r*68 + c4*4];
        d[0]=to_tf32(v.x); d[1]=to_tf32(v.y); d[2]=to_tf32(v.z); d[3]=to_tf32(v.w);
    }

    float m_run = -INFINITY, d_run = 0.f;

    wmma::fragment<wmma::accumulator,16,16,8,float> o[2];
    wmma::fill_fragment(o[0], 0.0f);
    wmma::fill_fragment(o[1], 0.0f);

    for(int k0=0; k0<CNK; k0+=128){
        __syncthreads();      // (a) KVs holds K

        uint32_t mb = mrow[(k0>>5) + sqtr];
        float4 vreg[4];
        #pragma unroll
        for(int i=0;i<4;i++){
            int id = tid + i*512;
            int r = id >> 4, c4 = id & 15;
            vreg[i] = *(const float4*)&Vb[(size_t)(k0+r)*CD + c4*4];
        }

        // ---- S = Qs @ K^T ----
        {
            wmma::fragment<wmma::accumulator,16,16,8,float> s[2][2];
            #pragma unroll
            for(int i=0;i<2;i++)
                #pragma unroll
                for(int j=0;j<2;j++) wmma::fill_fragment(s[i][j], 0.0f);
            #pragma unroll
            for(int d8=0; d8<CDH; d8+=8){
                wmma::fragment<wmma::matrix_a,16,16,8,wmma::precision::tf32,wmma::row_major> af[2];
                wmma::fragment<wmma::matrix_b,16,16,8,wmma::precision::tf32,wmma::col_major> bf[2];
                wmma::load_matrix_sync(af[0], &Qs[(wy*32)*68 + d8],      68);
                wmma::load_matrix_sync(af[1], &Qs[(wy*32+16)*68 + d8],   68);
                wmma::load_matrix_sync(bf[0], &KVs[(wx*32)*68 + d8],     68);
                wmma::load_matrix_sync(bf[1], &KVs[(wx*32+16)*68 + d8],  68);
                #pragma unroll
                for(int i=0;i<2;i++)
                    #pragma unroll
                    for(int j=0;j<2;j++)
                        wmma::mma_sync(s[i][j], af[i], bf[j], s[i][j]);
            }
            #pragma unroll
            for(int i=0;i<2;i++)
                #pragma unroll
                for(int j=0;j<2;j++)
                    wmma::store_matrix_sync(&Ss[(wy*32+i*16)*132 + wx*32 + j*16],
                                            s[i][j], 132, wmma::mem_row_major);
        }
        __syncthreads();      // (b) S done; KVs free for V

        #pragma unroll
        for(int i=0;i<4;i++){
            int id = tid + i*512;
            int r = id >> 4, c4 = id & 15;
            float* d = &KVs[r*68 + c4*4];
            d[0]=to_tf32(vreg[i].x); d[1]=to_tf32(vreg[i].y);
            d[2]=to_tf32(vreg[i].z); d[3]=to_tf32(vreg[i].w);
        }

        // ---- masked online softmax: 4 lanes/row, bitmask ----
        {
            float* sptr = &Ss[srow*132 + sqtr*32];
            float4 s4[8];
            #pragma unroll
            for(int i=0;i<8;i++) s4[i] = *(float4*)&sptr[i*4];

            float mx = -INFINITY;
            #pragma unroll
            for(int i=0;i<8;i++){
                s4[i].x = ((mb>>(4*i  ))&1u) ? s4[i].x : -1e9f;
                s4[i].y = ((mb>>(4*i+1))&1u) ? s4[i].y : -1e9f;
                s4[i].z = ((mb>>(4*i+2))&1u) ? s4[i].z : -1e9f;
                s4[i].w = ((mb>>(4*i+3))&1u) ? s4[i].w : -1e9f;
                mx = fmaxf(mx, fmaxf(fmaxf(s4[i].x,s4[i].y), fmaxf(s4[i].z,s4[i].w)));
            }
            mx = fmaxf(mx, __shfl_xor_sync(0xffffffffu, mx, 1));
            mx = fmaxf(mx, __shfl_xor_sync(0xffffffffu, mx, 2));

            float mn    = fmaxf(m_run, mx);
            float alpha = __expf(m_run - mn);
            float ps = 0.f;
            #pragma unroll
            for(int i=0;i<8;i++){
                float p0 = __expf(s4[i].x - mn), p1 = __expf(s4[i].y - mn);
                float p2 = __expf(s4[i].z - mn), p3 = __expf(s4[i].w - mn);
                ps += (p0+p1)+(p2+p3);
                s4[i].x = to_tf32(p0); s4[i].y = to_tf32(p1);
                s4[i].z = to_tf32(p2); s4[i].w = to_tf32(p3);
            }
            ps += __shfl_xor_sync(0xffffffffu, ps, 1);
            ps += __shfl_xor_sync(0xffffffffu, ps, 2);

            d_run = d_run*alpha + ps;
            m_run = mn;

            #pragma unroll
            for(int i=0;i<8;i++) *(float4*)&sptr[i*4] = s4[i];
            *(float4*)&aM[srow*20 + sqtr*4] = make_float4(alpha, alpha, alpha, alpha);
        }

        // stage next K (overlaps PV)
        float4 kreg[4];
        bool has_next = (k0 + 128 < CNK);
        if(has_next){
            #pragma unroll
            for(int i=0;i<4;i++){
                int id = tid + i*512;
                int r = id >> 4, c4 = id & 15;
                kreg[i] = *(const float4*)&Kb[(size_t)(k0+128+r)*CD + c4*4];
            }
        }
        __syncthreads();      // (c) probs + V + alpha visible

        // ---- O = O*alpha + P @ V ----
        {
            wmma::fragment<wmma::accumulator,16,16,8,float> afr;
            wmma::load_matrix_sync(afr, &aM[(wq*16)*20], 20, wmma::mem_row_major);
            #pragma unroll
            for(int e=0;e<afr.num_elements;e++){
                o[0].x[e] *= afr.x[e];
                o[1].x[e] *= afr.x[e];
            }
            #pragma unroll
            for(int ks=0;ks<16;ks++){
                wmma::fragment<wmma::matrix_a,16,16,8,wmma::precision::tf32,wmma::row_major> pa;
                wmma::fragment<wmma::matrix_b,16,16,8,wmma::precision::tf32,wmma::row_major> vb[2];
                wmma::load_matrix_sync(pa, &Ss[(wq*16)*132 + ks*8], 132);
                wmma::load_matrix_sync(vb[0], &KVs[(ks*8)*68 + wd*32],      68);
                wmma::load_matrix_sync(vb[1], &KVs[(ks*8)*68 + wd*32 + 16], 68);
                wmma::mma_sync(o[0], pa, vb[0], o[0]);
                wmma::mma_sync(o[1], pa, vb[1], o[1]);
            }
        }
        __syncthreads();      // (d) PV done reading KVs(V)

        if(has_next){
            #pragma unroll
            for(int i=0;i<4;i++){
                int id = tid + i*512;
                int r = id >> 4, c4 = id & 15;
                float* d = &KVs[r*68 + c4*4];
                d[0]=to_tf32(kreg[i].x); d[1]=to_tf32(kreg[i].y);
                d[2]=to_tf32(kreg[i].z); d[3]=to_tf32(kreg[i].w);
            }
        }
    }

    *(float4*)&aM[srow*20 + sqtr*4] =
        make_float4(1.0f/d_run, 1.0f/d_run, 1.0f/d_run, 1.0f/d_run);
    __syncthreads();
    {
        wmma::fragment<wmma::accumulator,16,16,8,float> ifr;
        wmma::load_matrix_sync(ifr, &aM[(wq*16)*20], 20, wmma::mem_row_major);
        #pragma unroll
        for(int e=0;e<ifr.num_elements;e++){
            o[0].x[e] *= ifr.x[e];
            o[1].x[e] *= ifr.x[e];
        }
        float* cb = ctx + ((size_t)(b*CNQ + q0 + wq*16))*CD + h*CDH + wd*32;
        wmma::store_matrix_sync(cb,      o[0], CD, wmma::mem_row_major);
        wmma::store_matrix_sync(cb + 16, o[1], CD, wmma::mem_row_major);
    }
}

// ------------------------- launch ------------------------------------------
extern "C" void kernel_launch(void* const* d_in, const int* in_sizes, int n_in,
                              void* d_out, int out_size){
    const float* in_upd  = (const float*)d_in[0];
    const float* emb     = (const float*)d_in[1];
    const float* maskL   = (const float*)d_in[2];
    const float* Wq      = (const float*)d_in[3];
    const float* Wk      = (const float*)d_in[4];
    const float* Wv      = (const float*)d_in[5];
    const float* Wo      = (const float*)d_in[6];
    const float* W1      = (const float*)d_in[7];
    const float* b1      = (const float*)d_in[8];
    const float* W2      = (const float*)d_in[9];
    const float* b2      = (const float*)d_in[10];
    const float* sys_s   = (const float*)d_in[11];
    const float* sys_b   = (const float*)d_in[12];
    const float* eff_s   = (const float*)d_in[13];
    const float* eff_b   = (const float*)d_in[14];
    const float* in_s    = (const float*)d_in[15];
    const float* in_b    = (const float*)d_in[16];
    const float* out_s   = (const float*)d_in[17];
    const float* out_b   = (const float*)d_in[18];
    const int*   qidxL   = (const int*)d_in[19];
    const int*   kidxL   = (const int*)d_in[20];
    float* outp = (float*)d_out;

    float *upd,*qb,*kb,*Qb,*Kb,*Vb,*ctx,*hb,*t1;
    uint32_t* mbits;
    cudaGetSymbolAddress((void**)&upd, g_upd);
    cudaGetSymbolAddress((void**)&qb,  g_q);
    cudaGetSymbolAddress((void**)&kb,  g_k);
    cudaGetSymbolAddress((void**)&Qb,  g_Qp);
    cudaGetSymbolAddress((void**)&Kb,  g_Kp);
    cudaGetSymbolAddress((void**)&Vb,  g_Vp);
    cudaGetSymbolAddress((void**)&ctx, g_ctx);
    cudaGetSymbolAddress((void**)&hb,  g_h);
    cudaGetSymbolAddress((void**)&t1,  g_t1);
    cudaGetSymbolAddress((void**)&mbits, g_mbits);

    const int flash_smem = FLASH_SMEM_FLOATS * (int)sizeof(float);  // ~144 KB
    const int ep_smem    = EP_SMEM_FLOATS    * (int)sizeof(float);  // ~66.6 KB
    cudaFuncSetAttribute(k_flash,   cudaFuncAttributeMaxDynamicSharedMemorySize,
                         flash_smem);
    cudaFuncSetAttribute(k_gemm_ep, cudaFuncAttributeMaxDynamicSharedMemorySize,
                         ep_smem);

    cudaMemsetAsync(d_out, 0, (size_t)out_size * sizeof(float));
    k_copy_upd<<<(CB*CNS*CD/4)/256, 256>>>((const float4*)in_upd);
    k_prep_mask<<<(CL*CNQ*NKW)/256, 256>>>(maskL);

    for(int l=0;l<CL;l++){
        const int* qi = qidxL + l*CNQ;
        const int* ki = kidxL + l*CNK;
        const uint32_t* mb = mbits + (size_t)l*CNQ*NKW;

        k_gather_ln<<<CB*CNQ, 256>>>(upd, emb, qi, sys_s, sys_b, qb, CNQ);
        k_gather_ln<<<CB*CNK, 256>>>(upd, emb, ki, sys_s, sys_b, kb, CNK);

        k_gemm_tc<<<dim3(CB*CNQ/128, 2), 256>>>(qb, Wq, nullptr, Qb, 0);
        k_gemm_tc<<<dim3(CB*CNK/128, 2), 256>>>(kb, Wk, nullptr, Kb, 0);
        k_gemm_tc<<<dim3(CB*CNK/128, 2), 256>>>(kb, Wv, nullptr, Vb, 0);

        k_flash<<<dim3(CNQ/128, CB*CH), 512, flash_smem>>>(Qb, Kb, Vb, mb, ctx);

        // Wo GEMM + inner LN fused -> hb
        k_gemm_ep<<<CB*CNQ/64, 256, ep_smem>>>(ctx, Wo, nullptr, nullptr,
                                               in_s, in_b, nullptr, nullptr,
                                               nullptr, hb, nullptr, 0);

        k_gemm_tc<<<dim3(CB*CNQ/128, 2), 256>>>(hb, W1, b1, t1, 1);   // gelu

        // W2 GEMM + residual + double LN + scatter-add fused
        k_gemm_ep<<<CB*CNQ/64, 256, ep_smem>>>(t1, W2, b2, hb,
                                               out_s, out_b, eff_s, eff_b,
                                               qi, upd, outp, 1);
    }
}